// round 10
// baseline (speedup 1.0000x reference)
#include <cuda_runtime.h>
#include <cuda_fp16.h>
#include <cstddef>

#define NN   50000
#define NE   800000
#define FIN  512
#define FHID 128
#define FOUT 64
#define SCAN_BLK 512
#define SCAN_NB  ((NN + SCAN_BLK - 1) / SCAN_BLK)   // 98

// ---------------- scratch (device globals) ---------------------------------
__device__ __align__(16) int    g_outdeg[NN];
__device__ __align__(16) int    g_indeg[NN];
__device__ __align__(16) float  g_onorm[NN];
__device__ __align__(16) float  g_inorm[NN];
__device__ __align__(16) int    g_rowptr[NN + 1];
__device__ __align__(16) int    g_cursor[NN];
__device__ __align__(16) int    g_srcs[NE];              // edge srcs sorted by dst
__device__ __align__(16) int    g_bsum[SCAN_NB];
__device__ __align__(16) int    g_boff[SCAN_NB];
__device__ __align__(16) float  g_W1p[FIN * FHID];       // W1 tf32, MMA-fragment-permuted
__device__ __align__(16) float  g_W2p[FHID * FOUT];      // W2 tf32, MMA-fragment-permuted
__device__ __align__(16) __half g_h1[(size_t)NN * FHID]; // x @ W1 (NO norm), fp16
__device__ __align__(16) __half g_h2[(size_t)NN * FOUT]; // x2 @ W2, fp16

#define CP_COMMIT() asm volatile("cp.async.commit_group;\n" ::: "memory")
#define CP_WAIT(n)  asm volatile("cp.async.wait_group %0;\n" :: "n"(n) : "memory")

__device__ __forceinline__ void cp_async16(void* smem, const void* g, bool pred) {
    unsigned saddr = (unsigned)__cvta_generic_to_shared(smem);
    int sz = pred ? 16 : 0;   // src-size 0 -> zero-fill, no read
    asm volatile("cp.async.cg.shared.global [%0], [%1], 16, %2;\n"
                 :: "r"(saddr), "l"(g), "r"(sz));
}

__device__ __forceinline__ unsigned f2tf32(float x) {
    unsigned r;
    asm("cvt.rna.tf32.f32 %0, %1;" : "=r"(r) : "f"(x));
    return r;
}

__device__ __forceinline__ void mma_tf32(float* c, const unsigned* a, const unsigned* b) {
    asm volatile(
        "mma.sync.aligned.m16n8k8.row.col.f32.tf32.tf32.f32 "
        "{%0,%1,%2,%3}, {%4,%5,%6,%7}, {%8,%9}, {%0,%1,%2,%3};"
        : "+f"(c[0]), "+f"(c[1]), "+f"(c[2]), "+f"(c[3])
        : "r"(a[0]), "r"(a[1]), "r"(a[2]), "r"(a[3]), "r"(b[0]), "r"(b[1]));
}

// accumulate 8 halves (uint4) scaled by s into a[0..7]
__device__ __forceinline__ void acc8(float* a, uint4 u, float s) {
    float2 f;
    f = __half22float2(*(__half2*)&u.x); a[0] = fmaf(f.x, s, a[0]); a[1] = fmaf(f.y, s, a[1]);
    f = __half22float2(*(__half2*)&u.y); a[2] = fmaf(f.x, s, a[2]); a[3] = fmaf(f.y, s, a[3]);
    f = __half22float2(*(__half2*)&u.z); a[4] = fmaf(f.x, s, a[4]); a[5] = fmaf(f.y, s, a[5]);
    f = __half22float2(*(__half2*)&u.w); a[6] = fmaf(f.x, s, a[6]); a[7] = fmaf(f.y, s, a[7]);
}

// ---------------- CSR build chain (side stream) -----------------------------
__global__ void zero_kernel() {
    int i = blockIdx.x * blockDim.x + threadIdx.x;
    if (i < NN) { g_outdeg[i] = 0; g_indeg[i] = 0; }
}

__global__ void hist_kernel(const int* __restrict__ src, const int* __restrict__ dst) {
    int base = blockIdx.x * blockDim.x * 4 + threadIdx.x;
#pragma unroll
    for (int k = 0; k < 4; k++) {
        int i = base + k * blockDim.x;
        if (i < NE) {
            atomicAdd(&g_outdeg[src[i]], 1);
            atomicAdd(&g_indeg[dst[i]], 1);
        }
    }
}

__global__ void scan_blocks_kernel() {
    __shared__ int sh[SCAN_BLK];
    int t = threadIdx.x;
    int idx = blockIdx.x * SCAN_BLK + t;
    int v = (idx < NN) ? g_indeg[idx] : 0;
    sh[t] = v;
    __syncthreads();
    for (int off = SCAN_BLK >> 1; off > 0; off >>= 1) {
        if (t < off) sh[t] += sh[t + off];
        __syncthreads();
    }
    if (t == 0) g_bsum[blockIdx.x] = sh[0];
}

__global__ void scan_tops_kernel() {
    __shared__ int sh[128];
    int t = threadIdx.x;
    int v = (t < SCAN_NB) ? g_bsum[t] : 0;
    sh[t] = v;
    __syncthreads();
    for (int off = 1; off < 128; off <<= 1) {
        int a = (t >= off) ? sh[t - off] : 0;
        __syncthreads();
        sh[t] += a;
        __syncthreads();
    }
    if (t < SCAN_NB) g_boff[t] = sh[t] - v;
}

__global__ void scan_final_kernel() {
    __shared__ int sh[SCAN_BLK];
    int t = threadIdx.x;
    int idx = blockIdx.x * SCAN_BLK + t;
    int v = (idx < NN) ? g_indeg[idx] : 0;
    sh[t] = v;
    __syncthreads();
    for (int off = 1; off < SCAN_BLK; off <<= 1) {
        int a = (t >= off) ? sh[t - off] : 0;
        __syncthreads();
        sh[t] += a;
        __syncthreads();
    }
    if (idx < NN) {
        int p = g_boff[blockIdx.x] + sh[t] - v;   // exclusive
        g_rowptr[idx] = p;
        g_cursor[idx] = p;
        g_onorm[idx] = rsqrtf(fmaxf((float)g_outdeg[idx], 1.0f));
        g_inorm[idx] = rsqrtf(fmaxf((float)v, 1.0f));
        if (idx == NN - 1) g_rowptr[NN] = NE;
    }
}

__global__ void place_kernel(const int* __restrict__ src, const int* __restrict__ dst) {
    int base = blockIdx.x * blockDim.x * 4 + threadIdx.x;
#pragma unroll
    for (int k = 0; k < 4; k++) {
        int i = base + k * blockDim.x;
        if (i < NE) {
            int p = atomicAdd(&g_cursor[dst[i]], 1);
            g_srcs[p] = src[i];
        }
    }
}

// ---------------- weight prep: tf32 round + fragment permutation ------------
__global__ void cvtW_kernel(const float* __restrict__ W1, const float* __restrict__ W2) {
    int i = blockIdx.x * blockDim.x + threadIdx.x;
    if (i < FIN * FHID) {
        int p = i >> 1, f = i & 1;
        int l = p & 31, cb = (p >> 5) & 15, ks = (p >> 9) & 3, it = p >> 11;
        int srow = it * 32 + ks * 8 + f * 4 + (l & 3);
        int scol = cb * 8 + (l >> 2);
        g_W1p[i] = __uint_as_float(f2tf32(W1[srow * FHID + scol]));
    } else if (i < FIN * FHID + FHID * FOUT) {
        int j = i - FIN * FHID;
        int p = j >> 1, f = j & 1;
        int l = p & 31, cb = (p >> 5) & 7, ksg = p >> 8;
        int srow = ksg * 8 + f * 4 + (l & 3);
        int scol = cb * 8 + (l >> 2);
        g_W2p[j] = __uint_as_float(f2tf32(W2[srow * FOUT + scol]));
    }
}

// ---------------- GEMM1 (tf32 MMA, 3-stage cp.async pipeline) ---------------
// h1 = x @ W1 (no norm), fp16 out. BM=128, BN=128, BK=32, 8 warps (4x2).
#define AS_STRIDE 36   // words; A-frag reads hit 32 distinct banks, 16B rows
#define BSTAGE    (32 * 128)   // 4096 words, dense permuted
__global__ __launch_bounds__(256, 1) void gemm1_kernel(const float* __restrict__ A) {
    __shared__ float As[3][128 * AS_STRIDE];
    __shared__ float Bs[3][BSTAGE];
    const int tid  = threadIdx.x;
    const int wid  = tid >> 5;
    const int lane = tid & 31;
    const int row0 = blockIdx.x * 128;
    const int warp_m = wid >> 1;
    const int warp_n = wid & 1;
    const int lq = lane >> 2;
    const int lr = lane & 3;

    float acc[2][8][4];
#pragma unroll
    for (int mt = 0; mt < 2; mt++)
#pragma unroll
        for (int nt = 0; nt < 8; nt++)
#pragma unroll
            for (int q = 0; q < 4; q++) acc[mt][nt][q] = 0.f;

    auto load_stage = [&](int buf, int it) {
        int k0 = it * 32;
#pragma unroll
        for (int l = tid; l < 128 * 8; l += 256) {      // A: 128x32
            int r = l >> 3, c4 = l & 7;
            int grow = row0 + r;
            bool ok = grow < NN;
            const float* gp = A + (size_t)(ok ? grow : 0) * FIN + k0 + (c4 << 2);
            cp_async16(&As[buf][r * AS_STRIDE + (c4 << 2)], gp, ok);
        }
        const float* bg = g_W1p + (size_t)it * BSTAGE;
#pragma unroll
        for (int l = tid; l < BSTAGE / 4; l += 256) {   // B: dense 16KB
            cp_async16(&Bs[buf][l << 2], bg + (l << 2), true);
        }
    };

    load_stage(0, 0); CP_COMMIT();
    load_stage(1, 1); CP_COMMIT();

    for (int it = 0; it < 16; ++it) {
        if (it < 15) CP_WAIT(1); else CP_WAIT(0);
        __syncthreads();   // stage `it` visible to all; all done with stage it-1
        const int buf = it % 3;
        const float* as = As[buf];
        const float* bs = Bs[buf];
#pragma unroll
        for (int ks = 0; ks < 4; ks++) {
            const int kk = ks << 3;
            unsigned af[2][4];
#pragma unroll
            for (int mt = 0; mt < 2; mt++) {
                int row = warp_m * 32 + mt * 16 + lq;
                af[mt][0] = f2tf32(as[row * AS_STRIDE + kk + lr]);
                af[mt][1] = f2tf32(as[(row + 8) * AS_STRIDE + kk + lr]);
                af[mt][2] = f2tf32(as[row * AS_STRIDE + kk + 4 + lr]);
                af[mt][3] = f2tf32(as[(row + 8) * AS_STRIDE + kk + 4 + lr]);
            }
            unsigned bf[8][2];
#pragma unroll
            for (int nt = 0; nt < 8; nt++) {
                int cb = warp_n * 8 + nt;
                const float2 bp = *(const float2*)&bs[((ks * 16 + cb) * 32 + lane) * 2];
                bf[nt][0] = __float_as_uint(bp.x);
                bf[nt][1] = __float_as_uint(bp.y);
            }
#pragma unroll
            for (int mt = 0; mt < 2; mt++)
#pragma unroll
                for (int nt = 0; nt < 8; nt++)
                    mma_tf32(acc[mt][nt], af[mt], bf[nt]);
        }
        if (it + 2 < 16) {   // prefetch distance 2; targets stage consumed at it-1
            load_stage((it + 2) % 3, it + 2);
            CP_COMMIT();
        }
    }

    // Epilogue: write fp16 (onorm applied at gather in layer2).
#pragma unroll
    for (int mt = 0; mt < 2; mt++) {
        int rowA = row0 + warp_m * 32 + mt * 16 + lq;
        int rowB = rowA + 8;
#pragma unroll
        for (int nt = 0; nt < 8; nt++) {
            int col = warp_n * 64 + nt * 8 + (lr << 1);
            if (rowA < NN)
                *(__half2*)(g_h1 + (size_t)rowA * FHID + col) =
                    __float22half2_rn(make_float2(acc[mt][nt][0], acc[mt][nt][1]));
            if (rowB < NN)
                *(__half2*)(g_h1 + (size_t)rowB * FHID + col) =
                    __float22half2_rn(make_float2(acc[mt][nt][2], acc[mt][nt][3]));
        }
    }
}

// ---------------- layer2: fused agg1 + epilogue1 + GEMM2 (tf32 MMA) --------
// Gather: half-warp per row (lane q in [0,16) loads 8 halves = 16B), rows
// advance in parallel per warp. x2 -> smem; h2 = x2 @ W2 tensor cores -> fp16.
__global__ __launch_bounds__(256) void layer2_kernel(const float* __restrict__ b1) {
    __shared__ float Ws[FHID * FOUT];   // 8192 words, dense permuted W2p
    __shared__ float x2s[32][132];
    const int tid  = threadIdx.x;
    const int wid  = tid >> 5;
    const int lane = tid & 31;
    const int r0 = blockIdx.x * 32;

    // W2p: dense 32KB copy
#pragma unroll
    for (int l = tid; l < FHID * FOUT / 4; l += 256)
        *(float4*)&Ws[l << 2] = *(const float4*)&g_W2p[l << 2];

    // Gather + epilogue1: warp handles 4 rows as 2 pairs (sub = half-warp)
    {
        const int sub = lane >> 4;     // 0,1
        const int q   = lane & 15;     // 0..15 -> halves [q*8, q*8+8)
        float4 bb0 = *(const float4*)(b1 + q * 8);
        float4 bb1 = *(const float4*)(b1 + q * 8 + 4);
#pragma unroll
        for (int p = 0; p < 2; p++) {
            int rloc = wid * 4 + p * 2 + sub;
            int row = r0 + rloc;
            float a[8] = {0.f, 0.f, 0.f, 0.f, 0.f, 0.f, 0.f, 0.f};
            float4 o0 = make_float4(0.f, 0.f, 0.f, 0.f);
            float4 o1 = make_float4(0.f, 0.f, 0.f, 0.f);
            if (row < NN) {
                int beg = g_rowptr[row], end = g_rowptr[row + 1];
                int e = beg;
                for (; e + 1 < end; e += 2) {
                    int s0 = g_srcs[e], s1 = g_srcs[e + 1];
                    uint4 u0 = *(const uint4*)(g_h1 + (size_t)s0 * FHID + q * 8);
                    uint4 u1 = *(const uint4*)(g_h1 + (size_t)s1 * FHID + q * 8);
                    float os0 = g_onorm[s0], os1 = g_onorm[s1];
                    acc8(a, u0, os0);
                    acc8(a, u1, os1);
                }
                if (e < end) {
                    int s0 = g_srcs[e];
                    uint4 u0 = *(const uint4*)(g_h1 + (size_t)s0 * FHID + q * 8);
                    acc8(a, u0, g_onorm[s0]);
                }
                float inn = g_inorm[row], onn = g_inorm[row] * 0.f + g_onorm[row];
                o0.x = fmaxf(fmaf(a[0], inn, bb0.x), 0.f) * onn;
                o0.y = fmaxf(fmaf(a[1], inn, bb0.y), 0.f) * onn;
                o0.z = fmaxf(fmaf(a[2], inn, bb0.z), 0.f) * onn;
                o0.w = fmaxf(fmaf(a[3], inn, bb0.w), 0.f) * onn;
                o1.x = fmaxf(fmaf(a[4], inn, bb1.x), 0.f) * onn;
                o1.y = fmaxf(fmaf(a[5], inn, bb1.y), 0.f) * onn;
                o1.z = fmaxf(fmaf(a[6], inn, bb1.z), 0.f) * onn;
                o1.w = fmaxf(fmaf(a[7], inn, bb1.w), 0.f) * onn;
            }
            *(float4*)&x2s[rloc][q * 8]     = o0;
            *(float4*)&x2s[rloc][q * 8 + 4] = o1;
        }
    }
    __syncthreads();

    // MMA phase: warp_m = wid>>2 (0..1), warp_n = wid&3 (0..3); 16x16 tile.
    const int lq = lane >> 2;
    const int lr = lane & 3;
    const int warp_m = wid >> 2;
    const int warp_n = wid & 3;
    float acc[2][4] = {{0.f, 0.f, 0.f, 0.f}, {0.f, 0.f, 0.f, 0.f}};
    const int arow = warp_m * 16 + lq;
#pragma unroll
    for (int ks = 0; ks < 16; ks++) {
        const int kk = ks << 3;
        unsigned af[4];
        af[0] = f2tf32(x2s[arow][kk + lr]);
        af[1] = f2tf32(x2s[arow + 8][kk + lr]);
        af[2] = f2tf32(x2s[arow][kk + 4 + lr]);
        af[3] = f2tf32(x2s[arow + 8][kk + 4 + lr]);
        unsigned bf[2][2];
#pragma unroll
        for (int nt = 0; nt < 2; nt++) {
            int cb = warp_n * 2 + nt;
            const float2 bp = *(const float2*)&Ws[((ks * 8 + cb) * 32 + lane) * 2];
            bf[nt][0] = __float_as_uint(bp.x);
            bf[nt][1] = __float_as_uint(bp.y);
        }
        mma_tf32(acc[0], af, bf[0]);
        mma_tf32(acc[1], af, bf[1]);
    }
    int rowA = r0 + warp_m * 16 + lq;
    int rowB = rowA + 8;
#pragma unroll
    for (int nt = 0; nt < 2; nt++) {
        int col = warp_n * 16 + nt * 8 + (lr << 1);
        if (rowA < NN)
            *(__half2*)(g_h2 + (size_t)rowA * FOUT + col) =
                __float22half2_rn(make_float2(acc[nt][0], acc[nt][1]));
        if (rowB < NN)
            *(__half2*)(g_h2 + (size_t)rowB * FOUT + col) =
                __float22half2_rn(make_float2(acc[nt][2], acc[nt][3]));
    }
}

// ---------------- agg2: 4 dst per warp (8 lanes x uint4 each) ---------------
// out = segsum(h2[src]) * inorm + b2
__global__ void agg2_kernel(const float* __restrict__ b2, float* __restrict__ out) {
    int gw = (int)(((long long)blockIdx.x * blockDim.x + threadIdx.x) >> 5);
    int lane = threadIdx.x & 31;
    int sub = lane >> 3;           // 0..3
    int q = lane & 7;              // halves [q*8, q*8+8)
    int d = gw * 4 + sub;
    if (d >= NN) return;
    int beg = g_rowptr[d], end = g_rowptr[d + 1];
    float a[8] = {0.f, 0.f, 0.f, 0.f, 0.f, 0.f, 0.f, 0.f};
    int e = beg;
    for (; e + 1 < end; e += 2) {
        int s0 = g_srcs[e], s1 = g_srcs[e + 1];
        uint4 u0 = *(const uint4*)(g_h2 + (size_t)s0 * FOUT + q * 8);
        uint4 u1 = *(const uint4*)(g_h2 + (size_t)s1 * FOUT + q * 8);
        acc8(a, u0, 1.0f);
        acc8(a, u1, 1.0f);
    }
    if (e < end) {
        int s0 = g_srcs[e];
        uint4 u0 = *(const uint4*)(g_h2 + (size_t)s0 * FOUT + q * 8);
        acc8(a, u0, 1.0f);
    }
    float inn = g_inorm[d];
    float4 bb0 = *(const float4*)(b2 + q * 8);
    float4 bb1 = *(const float4*)(b2 + q * 8 + 4);
    float4 r0, r1;
    r0.x = fmaf(a[0], inn, bb0.x); r0.y = fmaf(a[1], inn, bb0.y);
    r0.z = fmaf(a[2], inn, bb0.z); r0.w = fmaf(a[3], inn, bb0.w);
    r1.x = fmaf(a[4], inn, bb1.x); r1.y = fmaf(a[5], inn, bb1.y);
    r1.z = fmaf(a[6], inn, bb1.z); r1.w = fmaf(a[7], inn, bb1.w);
    *(float4*)(out + (size_t)d * FOUT + q * 8)     = r0;
    *(float4*)(out + (size_t)d * FOUT + q * 8 + 4) = r1;
}

// ---------------- launch: fork CSR chain onto side stream ------------------
extern "C" void kernel_launch(void* const* d_in, const int* in_sizes, int n_in,
                              void* d_out, int out_size) {
    const float* features = (const float*)d_in[0];
    const int*   esrc     = (const int*)d_in[1];
    const int*   edst     = (const int*)d_in[2];
    const float* W1       = (const float*)d_in[3];
    const float* b1       = (const float*)d_in[4];
    const float* W2       = (const float*)d_in[5];
    const float* b2       = (const float*)d_in[6];
    float* out = (float*)d_out;

    static cudaStream_t s1 = nullptr;
    static cudaEvent_t evFork = nullptr, evJoin = nullptr;
    if (s1 == nullptr) {
        cudaStreamCreateWithFlags(&s1, cudaStreamNonBlocking);
        cudaEventCreateWithFlags(&evFork, cudaEventDisableTiming);
        cudaEventCreateWithFlags(&evJoin, cudaEventDisableTiming);
    }

    cudaEventRecord(evFork, 0);
    cudaStreamWaitEvent(s1, evFork, 0);

    zero_kernel<<<(NN + 255) / 256, 256, 0, s1>>>();
    hist_kernel<<<(NE + 1023) / 1024, 256, 0, s1>>>(esrc, edst);
    scan_blocks_kernel<<<SCAN_NB, SCAN_BLK, 0, s1>>>();
    scan_tops_kernel<<<1, 128, 0, s1>>>();
    scan_final_kernel<<<SCAN_NB, SCAN_BLK, 0, s1>>>();
    place_kernel<<<(NE + 1023) / 1024, 256, 0, s1>>>(esrc, edst);
    cudaEventRecord(evJoin, s1);

    cvtW_kernel<<<(FIN * FHID + FHID * FOUT + 255) / 256, 256>>>(W1, W2);
    gemm1_kernel<<<(NN + 127) / 128, 256>>>(features);

    cudaStreamWaitEvent(0, evJoin, 0);
    layer2_kernel<<<(NN + 31) / 32, 256>>>(b1);
    agg2_kernel<<<(((NN + 3) / 4) * 32 + 255) / 256, 256>>>(b2, out);
}

// round 11
// speedup vs baseline: 1.0464x; 1.0464x over previous
#include <cuda_runtime.h>
#include <cuda_fp16.h>
#include <cstddef>

#define NN   50000
#define NE   800000
#define FIN  512
#define FHID 128
#define FOUT 64
#define SCAN_BLK 512
#define SCAN_NB  ((NN + SCAN_BLK - 1) / SCAN_BLK)   // 98
#define NTILES   ((NN + 127) / 128)                 // 391
#define GRID1    148

// ---------------- scratch (device globals) ---------------------------------
// g_outdeg/g_indeg invariant: zero at entry of every kernel_launch (zero at
// module load; agg2 re-zeroes them at the end of every launch).
__device__ __align__(16) int    g_outdeg[NN];
__device__ __align__(16) int    g_indeg[NN];
__device__ __align__(16) float  g_onorm[NN];
__device__ __align__(16) float  g_inorm[NN];
__device__ __align__(16) int    g_rowptr[NN + 1];
__device__ __align__(16) int    g_cursor[NN];
__device__ __align__(16) int    g_srcs[NE];              // edge srcs sorted by dst
__device__ __align__(16) int    g_bsum[SCAN_NB];
__device__ __align__(16) int    g_boff[SCAN_NB];
__device__ __align__(16) float  g_W1p[FIN * FHID];       // W1 tf32, MMA-fragment-permuted
__device__ __align__(16) float  g_W2p[FHID * FOUT];      // W2 tf32, MMA-fragment-permuted
__device__ __align__(16) __half g_h1[(size_t)NN * FHID]; // x @ W1 (NO norm), fp16
__device__ __align__(16) __half g_h2[(size_t)NN * FOUT]; // x2 @ W2, fp16

#define CP_COMMIT() asm volatile("cp.async.commit_group;\n" ::: "memory")
#define CP_WAIT(n)  asm volatile("cp.async.wait_group %0;\n" :: "n"(n) : "memory")

__device__ __forceinline__ void cp_async16(void* smem, const void* g, bool pred) {
    unsigned saddr = (unsigned)__cvta_generic_to_shared(smem);
    int sz = pred ? 16 : 0;   // src-size 0 -> zero-fill, no read
    asm volatile("cp.async.cg.shared.global [%0], [%1], 16, %2;\n"
                 :: "r"(saddr), "l"(g), "r"(sz));
}

__device__ __forceinline__ unsigned f2tf32(float x) {
    unsigned r;
    asm("cvt.rna.tf32.f32 %0, %1;" : "=r"(r) : "f"(x));
    return r;
}

__device__ __forceinline__ void mma_tf32(float* c, const unsigned* a, const unsigned* b) {
    asm volatile(
        "mma.sync.aligned.m16n8k8.row.col.f32.tf32.tf32.f32 "
        "{%0,%1,%2,%3}, {%4,%5,%6,%7}, {%8,%9}, {%0,%1,%2,%3};"
        : "+f"(c[0]), "+f"(c[1]), "+f"(c[2]), "+f"(c[3])
        : "r"(a[0]), "r"(a[1]), "r"(a[2]), "r"(a[3]), "r"(b[0]), "r"(b[1]));
}

// accumulate 8 halves (uint4) scaled by s into a[0..7]
__device__ __forceinline__ void acc8(float* a, uint4 u, float s) {
    float2 f;
    f = __half22float2(*(__half2*)&u.x); a[0] = fmaf(f.x, s, a[0]); a[1] = fmaf(f.y, s, a[1]);
    f = __half22float2(*(__half2*)&u.y); a[2] = fmaf(f.x, s, a[2]); a[3] = fmaf(f.y, s, a[3]);
    f = __half22float2(*(__half2*)&u.z); a[4] = fmaf(f.x, s, a[4]); a[5] = fmaf(f.y, s, a[5]);
    f = __half22float2(*(__half2*)&u.w); a[6] = fmaf(f.x, s, a[6]); a[7] = fmaf(f.y, s, a[7]);
}

// ---------------- CSR build chain (side stream) -----------------------------
__global__ void hist_kernel(const int* __restrict__ src, const int* __restrict__ dst) {
    int base = blockIdx.x * blockDim.x * 4 + threadIdx.x;
#pragma unroll
    for (int k = 0; k < 4; k++) {
        int i = base + k * blockDim.x;
        if (i < NE) {
            atomicAdd(&g_outdeg[src[i]], 1);
            atomicAdd(&g_indeg[dst[i]], 1);
        }
    }
}

__global__ void scan_blocks_kernel() {
    __shared__ int sh[SCAN_BLK];
    int t = threadIdx.x;
    int idx = blockIdx.x * SCAN_BLK + t;
    int v = (idx < NN) ? g_indeg[idx] : 0;
    sh[t] = v;
    __syncthreads();
    for (int off = SCAN_BLK >> 1; off > 0; off >>= 1) {
        if (t < off) sh[t] += sh[t + off];
        __syncthreads();
    }
    if (t == 0) g_bsum[blockIdx.x] = sh[0];
}

__global__ void scan_tops_kernel() {
    __shared__ int sh[128];
    int t = threadIdx.x;
    int v = (t < SCAN_NB) ? g_bsum[t] : 0;
    sh[t] = v;
    __syncthreads();
    for (int off = 1; off < 128; off <<= 1) {
        int a = (t >= off) ? sh[t - off] : 0;
        __syncthreads();
        sh[t] += a;
        __syncthreads();
    }
    if (t < SCAN_NB) g_boff[t] = sh[t] - v;
}

__global__ void scan_final_kernel() {
    __shared__ int sh[SCAN_BLK];
    int t = threadIdx.x;
    int idx = blockIdx.x * SCAN_BLK + t;
    int v = (idx < NN) ? g_indeg[idx] : 0;
    sh[t] = v;
    __syncthreads();
    for (int off = 1; off < SCAN_BLK; off <<= 1) {
        int a = (t >= off) ? sh[t - off] : 0;
        __syncthreads();
        sh[t] += a;
        __syncthreads();
    }
    if (idx < NN) {
        int p = g_boff[blockIdx.x] + sh[t] - v;   // exclusive
        g_rowptr[idx] = p;
        g_cursor[idx] = p;
        g_onorm[idx] = rsqrtf(fmaxf((float)g_outdeg[idx], 1.0f));
        g_inorm[idx] = rsqrtf(fmaxf((float)v, 1.0f));
        if (idx == NN - 1) g_rowptr[NN] = NE;
    }
}

__global__ void place_kernel(const int* __restrict__ src, const int* __restrict__ dst) {
    int base = blockIdx.x * blockDim.x * 8 + threadIdx.x;
#pragma unroll
    for (int k = 0; k < 8; k++) {
        int i = base + k * blockDim.x;
        if (i < NE) {
            int p = atomicAdd(&g_cursor[dst[i]], 1);
            g_srcs[p] = src[i];
        }
    }
}

// ---------------- weight prep: tf32 round + fragment permutation ------------
__global__ void cvtW_kernel(const float* __restrict__ W1, const float* __restrict__ W2) {
    int i = blockIdx.x * blockDim.x + threadIdx.x;
    if (i < FIN * FHID) {
        int p = i >> 1, f = i & 1;
        int l = p & 31, cb = (p >> 5) & 15, ks = (p >> 9) & 3, it = p >> 11;
        int srow = it * 32 + ks * 8 + f * 4 + (l & 3);
        int scol = cb * 8 + (l >> 2);
        g_W1p[i] = __uint_as_float(f2tf32(W1[srow * FHID + scol]));
    } else if (i < FIN * FHID + FHID * FOUT) {
        int j = i - FIN * FHID;
        int p = j >> 1, f = j & 1;
        int l = p & 31, cb = (p >> 5) & 7, ksg = p >> 8;
        int srow = ksg * 8 + f * 4 + (l & 3);
        int scol = cb * 8 + (l >> 2);
        g_W2p[j] = __uint_as_float(f2tf32(W2[srow * FOUT + scol]));
    }
}

// ---------------- GEMM1: persistent, tf32 MMA, 3-stage cp.async -------------
// h1 = x @ W1 (no norm), fp16 out. BM=128, BN=128, BK=32. grid=148, each block
// walks tiles b, b+148, ... with one flat pipeline (no drain between tiles).
#define AS_STRIDE 36   // words; A-frag reads hit 32 distinct banks, 16B rows
#define BSTAGE    (32 * 128)   // 4096 words, dense permuted
__global__ __launch_bounds__(256, 1) void gemm1_kernel(const float* __restrict__ A) {
    __shared__ float As[3][128 * AS_STRIDE];
    __shared__ float Bs[3][BSTAGE];
    const int tid  = threadIdx.x;
    const int wid  = tid >> 5;
    const int lane = tid & 31;
    const int warp_m = wid >> 1;
    const int warp_n = wid & 1;
    const int lq = lane >> 2;
    const int lr = lane & 3;

    const int my_nt = (NTILES - 1 - blockIdx.x) / GRID1 + 1;
    const int J = my_nt * 16;   // flat (tile, k-iter) iterations

    float acc[2][8][4];

    auto load_stage = [&](int buf, int j) {
        const int row0 = (blockIdx.x + (j >> 4) * GRID1) * 128;
        const int k0 = (j & 15) * 32;
#pragma unroll
        for (int l = tid; l < 128 * 8; l += 256) {      // A: 128x32
            int r = l >> 3, c4 = l & 7;
            int grow = row0 + r;
            bool ok = grow < NN;
            const float* gp = A + (size_t)(ok ? grow : 0) * FIN + k0 + (c4 << 2);
            cp_async16(&As[buf][r * AS_STRIDE + (c4 << 2)], gp, ok);
        }
        const float* bg = g_W1p + (size_t)(j & 15) * BSTAGE;
#pragma unroll
        for (int l = tid; l < BSTAGE / 4; l += 256) {   // B: dense 16KB
            cp_async16(&Bs[buf][l << 2], bg + (l << 2), true);
        }
    };

    load_stage(0, 0); CP_COMMIT();
    load_stage(1, 1); CP_COMMIT();

    for (int j = 0; j < J; ++j) {
        if (j + 1 < J) CP_WAIT(1); else CP_WAIT(0);
        __syncthreads();   // stage j visible; all warps done with stage j-1
        if ((j & 15) == 0) {
#pragma unroll
            for (int mt = 0; mt < 2; mt++)
#pragma unroll
                for (int nt = 0; nt < 8; nt++)
#pragma unroll
                    for (int q = 0; q < 4; q++) acc[mt][nt][q] = 0.f;
        }
        const int buf = j % 3;
        const float* as = As[buf];
        const float* bs = Bs[buf];
#pragma unroll
        for (int ks = 0; ks < 4; ks++) {
            const int kk = ks << 3;
            unsigned af[2][4];
#pragma unroll
            for (int mt = 0; mt < 2; mt++) {
                int row = warp_m * 32 + mt * 16 + lq;
                af[mt][0] = f2tf32(as[row * AS_STRIDE + kk + lr]);
                af[mt][1] = f2tf32(as[(row + 8) * AS_STRIDE + kk + lr]);
                af[mt][2] = f2tf32(as[row * AS_STRIDE + kk + 4 + lr]);
                af[mt][3] = f2tf32(as[(row + 8) * AS_STRIDE + kk + 4 + lr]);
            }
            unsigned bf[8][2];
#pragma unroll
            for (int nt = 0; nt < 8; nt++) {
                int cb = warp_n * 8 + nt;
                const float2 bp = *(const float2*)&bs[((ks * 16 + cb) * 32 + lane) * 2];
                bf[nt][0] = __float_as_uint(bp.x);
                bf[nt][1] = __float_as_uint(bp.y);
            }
#pragma unroll
            for (int mt = 0; mt < 2; mt++)
#pragma unroll
                for (int nt = 0; nt < 8; nt++)
                    mma_tf32(acc[mt][nt], af[mt], bf[nt]);
        }
        if (j + 2 < J) {   // prefetch distance 2; buffer consumed at j-1
            load_stage((j + 2) % 3, j + 2);
            CP_COMMIT();
        }
        if ((j & 15) == 15) {   // tile epilogue: regs -> gmem, overlaps prefetch
            const int row0 = (blockIdx.x + (j >> 4) * GRID1) * 128;
#pragma unroll
            for (int mt = 0; mt < 2; mt++) {
                int rowA = row0 + warp_m * 32 + mt * 16 + lq;
                int rowB = rowA + 8;
#pragma unroll
                for (int nt = 0; nt < 8; nt++) {
                    int col = warp_n * 64 + nt * 8 + (lr << 1);
                    if (rowA < NN)
                        *(__half2*)(g_h1 + (size_t)rowA * FHID + col) =
                            __float22half2_rn(make_float2(acc[mt][nt][0], acc[mt][nt][1]));
                    if (rowB < NN)
                        *(__half2*)(g_h1 + (size_t)rowB * FHID + col) =
                            __float22half2_rn(make_float2(acc[mt][nt][2], acc[mt][nt][3]));
                }
            }
        }
    }
}

// ---------------- layer2: fused agg1 + epilogue1 + GEMM2 (tf32 MMA) --------
__global__ __launch_bounds__(256) void layer2_kernel(const float* __restrict__ b1) {
    __shared__ float Ws[FHID * FOUT];   // 8192 words, dense permuted W2p
    __shared__ float x2s[32][132];
    const int tid  = threadIdx.x;
    const int wid  = tid >> 5;
    const int lane = tid & 31;
    const int r0 = blockIdx.x * 32;

#pragma unroll
    for (int l = tid; l < FHID * FOUT / 4; l += 256)
        *(float4*)&Ws[l << 2] = *(const float4*)&g_W2p[l << 2];

    // Gather + epilogue1: warp handles 4 rows as 2 pairs (sub = half-warp)
    {
        const int sub = lane >> 4;     // 0,1
        const int q   = lane & 15;     // 0..15 -> halves [q*8, q*8+8)
        float4 bb0 = *(const float4*)(b1 + q * 8);
        float4 bb1 = *(const float4*)(b1 + q * 8 + 4);
#pragma unroll
        for (int p = 0; p < 2; p++) {
            int rloc = wid * 4 + p * 2 + sub;
            int row = r0 + rloc;
            float a[8] = {0.f, 0.f, 0.f, 0.f, 0.f, 0.f, 0.f, 0.f};
            float4 o0 = make_float4(0.f, 0.f, 0.f, 0.f);
            float4 o1 = make_float4(0.f, 0.f, 0.f, 0.f);
            if (row < NN) {
                int beg = g_rowptr[row], end = g_rowptr[row + 1];
                int e = beg;
                for (; e + 1 < end; e += 2) {
                    int s0 = g_srcs[e], s1 = g_srcs[e + 1];
                    uint4 u0 = *(const uint4*)(g_h1 + (size_t)s0 * FHID + q * 8);
                    uint4 u1 = *(const uint4*)(g_h1 + (size_t)s1 * FHID + q * 8);
                    float os0 = g_onorm[s0], os1 = g_onorm[s1];
                    acc8(a, u0, os0);
                    acc8(a, u1, os1);
                }
                if (e < end) {
                    int s0 = g_srcs[e];
                    uint4 u0 = *(const uint4*)(g_h1 + (size_t)s0 * FHID + q * 8);
                    acc8(a, u0, g_onorm[s0]);
                }
                float inn = g_inorm[row], onn = g_onorm[row];
                o0.x = fmaxf(fmaf(a[0], inn, bb0.x), 0.f) * onn;
                o0.y = fmaxf(fmaf(a[1], inn, bb0.y), 0.f) * onn;
                o0.z = fmaxf(fmaf(a[2], inn, bb0.z), 0.f) * onn;
                o0.w = fmaxf(fmaf(a[3], inn, bb0.w), 0.f) * onn;
                o1.x = fmaxf(fmaf(a[4], inn, bb1.x), 0.f) * onn;
                o1.y = fmaxf(fmaf(a[5], inn, bb1.y), 0.f) * onn;
                o1.z = fmaxf(fmaf(a[6], inn, bb1.z), 0.f) * onn;
                o1.w = fmaxf(fmaf(a[7], inn, bb1.w), 0.f) * onn;
            }
            *(float4*)&x2s[rloc][q * 8]     = o0;
            *(float4*)&x2s[rloc][q * 8 + 4] = o1;
        }
    }
    __syncthreads();

    // MMA phase: warp_m = wid>>2 (0..1), warp_n = wid&3 (0..3); 16x16 tile.
    const int lq = lane >> 2;
    const int lr = lane & 3;
    const int warp_m = wid >> 2;
    const int warp_n = wid & 3;
    float acc[2][4] = {{0.f, 0.f, 0.f, 0.f}, {0.f, 0.f, 0.f, 0.f}};
    const int arow = warp_m * 16 + lq;
#pragma unroll
    for (int ks = 0; ks < 16; ks++) {
        const int kk = ks << 3;
        unsigned af[4];
        af[0] = f2tf32(x2s[arow][kk + lr]);
        af[1] = f2tf32(x2s[arow + 8][kk + lr]);
        af[2] = f2tf32(x2s[arow][kk + 4 + lr]);
        af[3] = f2tf32(x2s[arow + 8][kk + 4 + lr]);
        unsigned bf[2][2];
#pragma unroll
        for (int nt = 0; nt < 2; nt++) {
            int cb = warp_n * 2 + nt;
            const float2 bp = *(const float2*)&Ws[((ks * 8 + cb) * 32 + lane) * 2];
            bf[nt][0] = __float_as_uint(bp.x);
            bf[nt][1] = __float_as_uint(bp.y);
        }
        mma_tf32(acc[0], af, bf[0]);
        mma_tf32(acc[1], af, bf[1]);
    }
    int rowA = r0 + warp_m * 16 + lq;
    int rowB = rowA + 8;
#pragma unroll
    for (int nt = 0; nt < 2; nt++) {
        int col = warp_n * 16 + nt * 8 + (lr << 1);
        if (rowA < NN)
            *(__half2*)(g_h2 + (size_t)rowA * FOUT + col) =
                __float22half2_rn(make_float2(acc[nt][0], acc[nt][1]));
        if (rowB < NN)
            *(__half2*)(g_h2 + (size_t)rowB * FOUT + col) =
                __float22half2_rn(make_float2(acc[nt][2], acc[nt][3]));
    }
}

// ---------------- agg2: 4 dst per warp; re-zeroes degree arrays ------------
// out = segsum(h2[src]) * inorm + b2.  Tail: restore g_outdeg/g_indeg = 0 for
// the next launch (nothing reads them after this point in the DAG).
__global__ void agg2_kernel(const float* __restrict__ b2, float* __restrict__ out) {
    // re-zero degrees: block b covers nodes [b*32, b*32+32)
    {
        int z = blockIdx.x * 32 + threadIdx.x;
        if (threadIdx.x < 32 && z < NN) { g_outdeg[z] = 0; g_indeg[z] = 0; }
    }
    int gw = (int)(((long long)blockIdx.x * blockDim.x + threadIdx.x) >> 5);
    int lane = threadIdx.x & 31;
    int sub = lane >> 3;           // 0..3
    int q = lane & 7;              // halves [q*8, q*8+8)
    int d = gw * 4 + sub;
    if (d >= NN) return;
    int beg = g_rowptr[d], end = g_rowptr[d + 1];
    float a[8] = {0.f, 0.f, 0.f, 0.f, 0.f, 0.f, 0.f, 0.f};
    int e = beg;
    for (; e + 1 < end; e += 2) {
        int s0 = g_srcs[e], s1 = g_srcs[e + 1];
        uint4 u0 = *(const uint4*)(g_h2 + (size_t)s0 * FOUT + q * 8);
        uint4 u1 = *(const uint4*)(g_h2 + (size_t)s1 * FOUT + q * 8);
        acc8(a, u0, 1.0f);
        acc8(a, u1, 1.0f);
    }
    if (e < end) {
        int s0 = g_srcs[e];
        uint4 u0 = *(const uint4*)(g_h2 + (size_t)s0 * FOUT + q * 8);
        acc8(a, u0, 1.0f);
    }
    float inn = g_inorm[d];
    float4 bb0 = *(const float4*)(b2 + q * 8);
    float4 bb1 = *(const float4*)(b2 + q * 8 + 4);
    float4 r0, r1;
    r0.x = fmaf(a[0], inn, bb0.x); r0.y = fmaf(a[1], inn, bb0.y);
    r0.z = fmaf(a[2], inn, bb0.z); r0.w = fmaf(a[3], inn, bb0.w);
    r1.x = fmaf(a[4], inn, bb1.x); r1.y = fmaf(a[5], inn, bb1.y);
    r1.z = fmaf(a[6], inn, bb1.z); r1.w = fmaf(a[7], inn, bb1.w);
    *(float4*)(out + (size_t)d * FOUT + q * 8)     = r0;
    *(float4*)(out + (size_t)d * FOUT + q * 8 + 4) = r1;
}

// ---------------- launch: fork CSR chain onto side stream ------------------
// Submission order puts gemm1 at kernel-launch #6 so the ncu -s5 -c1 window
// captures it (events are not kernel launches; cross-stream submission order
// does not change the dependency DAG).
extern "C" void kernel_launch(void* const* d_in, const int* in_sizes, int n_in,
                              void* d_out, int out_size) {
    const float* features = (const float*)d_in[0];
    const int*   esrc     = (const int*)d_in[1];
    const int*   edst     = (const int*)d_in[2];
    const float* W1       = (const float*)d_in[3];
    const float* b1       = (const float*)d_in[4];
    const float* W2       = (const float*)d_in[5];
    const float* b2       = (const float*)d_in[6];
    float* out = (float*)d_out;

    static cudaStream_t s1 = nullptr;
    static cudaEvent_t evFork = nullptr, evJoin = nullptr;
    if (s1 == nullptr) {
        cudaStreamCreateWithFlags(&s1, cudaStreamNonBlocking);
        cudaEventCreateWithFlags(&evFork, cudaEventDisableTiming);
        cudaEventCreateWithFlags(&evJoin, cudaEventDisableTiming);
    }

    cudaEventRecord(evFork, 0);
    cudaStreamWaitEvent(s1, evFork, 0);

    cvtW_kernel<<<(FIN * FHID + FHID * FOUT + 255) / 256, 256>>>(W1, W2);  // #1 (main)
    hist_kernel<<<(NE + 1023) / 1024, 256, 0, s1>>>(esrc, edst);           // #2 (s1)
    scan_blocks_kernel<<<SCAN_NB, SCAN_BLK, 0, s1>>>();                    // #3
    scan_tops_kernel<<<1, 128, 0, s1>>>();                                 // #4
    scan_final_kernel<<<SCAN_NB, SCAN_BLK, 0, s1>>>();                     // #5
    gemm1_kernel<<<GRID1, 256>>>(features);                                // #6 (main)
    place_kernel<<<(NE + 2047) / 2048, 256, 0, s1>>>(esrc, edst);          // #7 (s1)
    cudaEventRecord(evJoin, s1);

    cudaStreamWaitEvent(0, evJoin, 0);
    layer2_kernel<<<(NN + 31) / 32, 256>>>(b1);                            // #8
    agg2_kernel<<<(NN + 31) / 32, 256>>>(b2, out);                         // #9
}